// round 1
// baseline (speedup 1.0000x reference)
#include <cuda_runtime.h>
#include <math.h>

// Problem constants
#define T_DIM 1024
#define B_DIM 8
#define D_DIM 1024
#define H_DIM 16
#define HD_DIM 64
#define M_ROWS (T_DIM * B_DIM)        // 8192
#define ROW_STRIDE (B_DIM * D_DIM)    // 8192 floats between consecutive t

// Scratch buffers (no cudaMalloc allowed) — 4 x 32 MB
__device__ float g_q[T_DIM * B_DIM * D_DIM];
__device__ float g_k[T_DIM * B_DIM * D_DIM];
__device__ float g_v[T_DIM * B_DIM * D_DIM];
__device__ float g_ctx[T_DIM * B_DIM * D_DIM];

// ---------------------------------------------------------------------------
// GEMM: C[M=8192][N=1024] = A[M][K=1024] @ W^T + bias,  W is [N][K] row-major
// 64x64 block tile, BK=16, 256 threads, 4x4 register micro-tile per thread.
// Both A and W tiles load coalesced as [row][k] with +1 pad.
// ---------------------------------------------------------------------------
__global__ __launch_bounds__(256) void gemm_bias_kernel(
    const float* __restrict__ A, const float* __restrict__ W,
    const float* __restrict__ bias, float* __restrict__ C) {
    __shared__ float As[64][17];
    __shared__ float Ws[64][17];

    const int tid = threadIdx.x;
    const int tx = tid & 15;        // column group (x4)
    const int ty = tid >> 4;        // row group (x4)
    const int row0 = blockIdx.y * 64;
    const int col0 = blockIdx.x * 64;

    float acc[4][4] = {};

    for (int k0 = 0; k0 < 1024; k0 += 16) {
        // 64x16 = 1024 elems each, 4 per thread, coalesced rows of 16 floats
        #pragma unroll
        for (int i = tid; i < 64 * 16; i += 256) {
            int r = i >> 4, c = i & 15;
            As[r][c] = A[(size_t)(row0 + r) * 1024 + k0 + c];
            Ws[r][c] = W[(size_t)(col0 + r) * 1024 + k0 + c];
        }
        __syncthreads();

        #pragma unroll
        for (int kk = 0; kk < 16; kk++) {
            float a[4], b[4];
            #pragma unroll
            for (int i = 0; i < 4; i++) a[i] = As[ty * 4 + i][kk];
            #pragma unroll
            for (int j = 0; j < 4; j++) b[j] = Ws[tx * 4 + j][kk];
            #pragma unroll
            for (int i = 0; i < 4; i++)
                #pragma unroll
                for (int j = 0; j < 4; j++)
                    acc[i][j] += a[i] * b[j];
        }
        __syncthreads();
    }

    #pragma unroll
    for (int j = 0; j < 4; j++) {
        float bj = bias[col0 + tx * 4 + j];
        #pragma unroll
        for (int i = 0; i < 4; i++)
            C[(size_t)(row0 + ty * 4 + i) * 1024 + col0 + tx * 4 + j] =
                acc[i][j] + bj;
    }
}

// ---------------------------------------------------------------------------
// Flash-style attention. One CTA = one (b,h) head x 64 query rows.
// 256 threads as 16x16; each thread owns a 4x4 score/P micro-tile and a
// 4 rows x 4 dcols output accumulator. Online softmax state (m, l) is kept
// in registers, replicated across the 16 lanes of a row-group via shuffles.
// Q is pre-scaled by 1/sqrt(HD) at load.
// ---------------------------------------------------------------------------
#define ATTN_SMEM (4 * 64 * 65 * 4)   // Qs, Ks, Vs, Ps  = 66560 bytes

__global__ __launch_bounds__(256) void attn_kernel(
    const float* __restrict__ qb, const float* __restrict__ kb,
    const float* __restrict__ vb, float* __restrict__ cb) {
    extern __shared__ float sm[];
    float* Qs = sm;                 // [64][65]
    float* Ks = Qs + 64 * 65;
    float* Vs = Ks + 64 * 65;
    float* Ps = Vs + 64 * 65;

    const int tid = threadIdx.x;
    const int tx = tid & 15;
    const int ty = tid >> 4;
    const int t0 = blockIdx.x * 64;
    const int bh = blockIdx.y;
    const int b = bh >> 4;
    const int h = bh & 15;
    const size_t headoff = (size_t)b * D_DIM + (size_t)h * HD_DIM;
    const float scale = 0.125f;     // 1/sqrt(64)

    // Load Q tile (pre-scaled)
    for (int i = tid; i < 64 * 64; i += 256) {
        int r = i >> 6, c = i & 63;
        Qs[r * 65 + c] =
            qb[(size_t)(t0 + r) * ROW_STRIDE + headoff + c] * scale;
    }

    float m[4], l[4], o[4][4];
    #pragma unroll
    for (int i = 0; i < 4; i++) {
        m[i] = -INFINITY;
        l[i] = 0.0f;
        #pragma unroll
        for (int j = 0; j < 4; j++) o[i][j] = 0.0f;
    }
    __syncthreads();

    for (int j0 = 0; j0 < T_DIM; j0 += 64) {
        // Load K, V tiles
        for (int i = tid; i < 64 * 64; i += 256) {
            int r = i >> 6, c = i & 63;
            size_t g = (size_t)(j0 + r) * ROW_STRIDE + headoff + c;
            Ks[r * 65 + c] = kb[g];
            Vs[r * 65 + c] = vb[g];
        }
        __syncthreads();

        // S = Q K^T (4x4 per thread)
        float s[4][4] = {};
        #pragma unroll 8
        for (int kk = 0; kk < 64; kk++) {
            float a[4], bv4[4];
            #pragma unroll
            for (int i = 0; i < 4; i++) a[i] = Qs[(ty * 4 + i) * 65 + kk];
            #pragma unroll
            for (int j = 0; j < 4; j++) bv4[j] = Ks[(tx * 4 + j) * 65 + kk];
            #pragma unroll
            for (int i = 0; i < 4; i++)
                #pragma unroll
                for (int j = 0; j < 4; j++)
                    s[i][j] += a[i] * bv4[j];
        }

        // Online softmax per row; lanes sharing a row (same ty, 16 tx)
        // reduce via shfl.xor within their 16-lane half-warp.
        #pragma unroll
        for (int i = 0; i < 4; i++) {
            float tm = s[i][0];
            #pragma unroll
            for (int j = 1; j < 4; j++) tm = fmaxf(tm, s[i][j]);
            tm = fmaxf(tm, __shfl_xor_sync(0xffffffffu, tm, 1));
            tm = fmaxf(tm, __shfl_xor_sync(0xffffffffu, tm, 2));
            tm = fmaxf(tm, __shfl_xor_sync(0xffffffffu, tm, 4));
            tm = fmaxf(tm, __shfl_xor_sync(0xffffffffu, tm, 8));

            float mn = fmaxf(m[i], tm);
            float alpha = __expf(m[i] - mn);
            m[i] = mn;

            float ps = 0.0f;
            #pragma unroll
            for (int j = 0; j < 4; j++) {
                s[i][j] = __expf(s[i][j] - mn);
                ps += s[i][j];
            }
            ps += __shfl_xor_sync(0xffffffffu, ps, 1);
            ps += __shfl_xor_sync(0xffffffffu, ps, 2);
            ps += __shfl_xor_sync(0xffffffffu, ps, 4);
            ps += __shfl_xor_sync(0xffffffffu, ps, 8);

            l[i] = l[i] * alpha + ps;
            #pragma unroll
            for (int j = 0; j < 4; j++) o[i][j] *= alpha;
            #pragma unroll
            for (int j = 0; j < 4; j++)
                Ps[(ty * 4 + i) * 65 + tx * 4 + j] = s[i][j];
        }
        __syncthreads();

        // O += P V  (thread owns rows ty*4+i, dcols tx*4+j)
        #pragma unroll 8
        for (int c = 0; c < 64; c++) {
            float vv[4];
            #pragma unroll
            for (int j = 0; j < 4; j++) vv[j] = Vs[c * 65 + tx * 4 + j];
            #pragma unroll
            for (int i = 0; i < 4; i++) {
                float p = Ps[(ty * 4 + i) * 65 + c];
                #pragma unroll
                for (int j = 0; j < 4; j++) o[i][j] += p * vv[j];
            }
        }
        __syncthreads();   // before next tile overwrites Ks/Vs/Ps
    }

    // Normalize and write context as (t, b, h, d)
    #pragma unroll
    for (int i = 0; i < 4; i++) {
        float inv = 1.0f / l[i];
        #pragma unroll
        for (int j = 0; j < 4; j++)
            cb[(size_t)(t0 + ty * 4 + i) * ROW_STRIDE + headoff + tx * 4 + j] =
                o[i][j] * inv;
    }
}

// ---------------------------------------------------------------------------
// Launch
// ---------------------------------------------------------------------------
extern "C" void kernel_launch(void* const* d_in, const int* in_sizes, int n_in,
                              void* d_out, int out_size) {
    const float* query = (const float*)d_in[0];
    const float* key   = (const float*)d_in[1];
    const float* value = (const float*)d_in[2];
    const float* Wq = (const float*)d_in[3];
    const float* bq = (const float*)d_in[4];
    const float* Wk = (const float*)d_in[5];
    const float* bk = (const float*)d_in[6];
    const float* Wv = (const float*)d_in[7];
    const float* bv = (const float*)d_in[8];
    const float* Wo = (const float*)d_in[9];
    const float* bo = (const float*)d_in[10];
    float* out = (float*)d_out;

    float *qb, *kb, *vb, *cb;
    cudaGetSymbolAddress((void**)&qb, g_q);
    cudaGetSymbolAddress((void**)&kb, g_k);
    cudaGetSymbolAddress((void**)&vb, g_v);
    cudaGetSymbolAddress((void**)&cb, g_ctx);

    cudaFuncSetAttribute(attn_kernel,
                         cudaFuncAttributeMaxDynamicSharedMemorySize,
                         ATTN_SMEM);

    dim3 gemm_grid(1024 / 64, M_ROWS / 64);   // (16, 128)
    gemm_bias_kernel<<<gemm_grid, 256>>>(query, Wq, bq, qb);
    gemm_bias_kernel<<<gemm_grid, 256>>>(key,   Wk, bk, kb);
    gemm_bias_kernel<<<gemm_grid, 256>>>(value, Wv, bv, vb);

    dim3 attn_grid(T_DIM / 64, B_DIM * H_DIM);  // (16, 128)
    attn_kernel<<<attn_grid, 256, ATTN_SMEM>>>(qb, kb, vb, cb);

    gemm_bias_kernel<<<gemm_grid, 256>>>(cb, Wo, bo, out);
}

// round 2
// speedup vs baseline: 1.3314x; 1.3314x over previous
#include <cuda_runtime.h>
#include <math.h>

// Problem constants
#define T_DIM 1024
#define B_DIM 8
#define D_DIM 1024
#define H_DIM 16
#define HD_DIM 64
#define M_ROWS (T_DIM * B_DIM)        // 8192
#define ROW_STRIDE (B_DIM * D_DIM)    // 8192 floats between consecutive t

// Scratch buffers (no cudaMalloc allowed) — 4 x 32 MB
__device__ float g_q[T_DIM * B_DIM * D_DIM];
__device__ float g_k[T_DIM * B_DIM * D_DIM];
__device__ float g_v[T_DIM * B_DIM * D_DIM];
__device__ float g_ctx[T_DIM * B_DIM * D_DIM];

// ---------------------------------------------------------------------------
// SGEMM v2: C[8192][1024] = A @ W^T + bias, W is [N][K] row-major.
// 128x128 tile, BK=16, 256 threads, 8x8 micro-tile.
// Smem stored k-major (transposed) with XOR swizzle -> conflict-free STS and
// vectorized LDS.128 reads. Double-buffered stages, register-staged prefetch.
// ---------------------------------------------------------------------------
#define BM 128
#define BN 128
#define BK 16

__global__ __launch_bounds__(256, 2) void gemm_bias_kernel(
    const float* __restrict__ A, const float* __restrict__ W,
    const float* __restrict__ bias, float* __restrict__ C) {
    __shared__ float As[2][BK][BM];
    __shared__ float Ws[2][BK][BN];

    const int tid = threadIdx.x;
    const int tx = tid & 15;
    const int ty = tid >> 4;
    const int row0 = blockIdx.y * BM;
    const int col0 = blockIdx.x * BN;

    // loader coords: idx = u*256 + tid -> r = idx>>2 (0..127), c4 = idx&3
    const int r_ld = tid >> 2;     // 0..63 (u adds 64)
    const int c4 = tid & 3;
    const float* Aptr = A + (size_t)(row0 + r_ld) * 1024 + c4 * 4;
    const float* Wptr = W + (size_t)(col0 + r_ld) * 1024 + c4 * 4;

    float acc[8][8] = {};

    // prologue: fill stage 0
    #pragma unroll
    for (int u = 0; u < 2; u++) {
        float4 va = *(const float4*)(Aptr + (size_t)u * 64 * 1024);
        float4 vw = *(const float4*)(Wptr + (size_t)u * 64 * 1024);
        int rs = (r_ld + u * 64) ^ (c4 << 3);   // swizzle SW(k)=((k>>2)&3)<<3 = c4<<3
        int kb = c4 * 4;
        As[0][kb + 0][rs] = va.x; As[0][kb + 1][rs] = va.y;
        As[0][kb + 2][rs] = va.z; As[0][kb + 3][rs] = va.w;
        Ws[0][kb + 0][rs] = vw.x; Ws[0][kb + 1][rs] = vw.y;
        Ws[0][kb + 2][rs] = vw.z; Ws[0][kb + 3][rs] = vw.w;
    }
    __syncthreads();

    for (int k0 = 0; k0 < 1024; k0 += BK) {
        const int st = (k0 >> 4) & 1;
        const bool next = (k0 + BK) < 1024;
        float4 ra[2], rw[2];
        if (next) {
            #pragma unroll
            for (int u = 0; u < 2; u++) {
                ra[u] = *(const float4*)(Aptr + (size_t)u * 64 * 1024 + k0 + BK);
                rw[u] = *(const float4*)(Wptr + (size_t)u * 64 * 1024 + k0 + BK);
            }
        }

        #pragma unroll
        for (int kk = 0; kk < BK; kk++) {
            const int sw = ((kk >> 2) & 3) << 3;
            const int ca = (ty * 8) ^ sw;
            const int cb = (tx * 8) ^ sw;
            float4 a0 = *(const float4*)&As[st][kk][ca];
            float4 a1 = *(const float4*)&As[st][kk][ca + 4];
            float4 b0 = *(const float4*)&Ws[st][kk][cb];
            float4 b1 = *(const float4*)&Ws[st][kk][cb + 4];
            float av[8] = {a0.x, a0.y, a0.z, a0.w, a1.x, a1.y, a1.z, a1.w};
            float bv[8] = {b0.x, b0.y, b0.z, b0.w, b1.x, b1.y, b1.z, b1.w};
            #pragma unroll
            for (int i = 0; i < 8; i++)
                #pragma unroll
                for (int j = 0; j < 8; j++)
                    acc[i][j] += av[i] * bv[j];
        }

        if (next) {
            #pragma unroll
            for (int u = 0; u < 2; u++) {
                int rs = (r_ld + u * 64) ^ (c4 << 3);
                int kb = c4 * 4;
                As[st ^ 1][kb + 0][rs] = ra[u].x; As[st ^ 1][kb + 1][rs] = ra[u].y;
                As[st ^ 1][kb + 2][rs] = ra[u].z; As[st ^ 1][kb + 3][rs] = ra[u].w;
                Ws[st ^ 1][kb + 0][rs] = rw[u].x; Ws[st ^ 1][kb + 1][rs] = rw[u].y;
                Ws[st ^ 1][kb + 2][rs] = rw[u].z; Ws[st ^ 1][kb + 3][rs] = rw[u].w;
            }
        }
        __syncthreads();
    }

    // epilogue: bias + store (vectorized)
    float bj[8];
    {
        float4 bb0 = *(const float4*)&bias[col0 + tx * 8];
        float4 bb1 = *(const float4*)&bias[col0 + tx * 8 + 4];
        bj[0] = bb0.x; bj[1] = bb0.y; bj[2] = bb0.z; bj[3] = bb0.w;
        bj[4] = bb1.x; bj[5] = bb1.y; bj[6] = bb1.z; bj[7] = bb1.w;
    }
    #pragma unroll
    for (int i = 0; i < 8; i++) {
        size_t row = (size_t)(row0 + ty * 8 + i);
        #pragma unroll
        for (int j4 = 0; j4 < 2; j4++) {
            float4 o;
            o.x = acc[i][j4 * 4 + 0] + bj[j4 * 4 + 0];
            o.y = acc[i][j4 * 4 + 1] + bj[j4 * 4 + 1];
            o.z = acc[i][j4 * 4 + 2] + bj[j4 * 4 + 2];
            o.w = acc[i][j4 * 4 + 3] + bj[j4 * 4 + 3];
            *(float4*)&C[row * 1024 + col0 + tx * 8 + j4 * 4] = o;
        }
    }
}

// ---------------------------------------------------------------------------
// Attention v2: flash-style, 64 q-rows x 64 k-cols per tile, 256 threads
// (16x16), 4x4 micro-tile. Q/K/P stored transposed (inner-dim-major) with
// XOR swizzle so QK^T and PV read 2 x LDS.128 per 16 FMA.
//   Qt[d][q], Kt[d][kc], Pt[kc][q]  (swizzled col),  Vs[kr][d] (row-major)
// Swizzle: col' = col ^ (((rowidx>>3)&3)<<2)
// ---------------------------------------------------------------------------
#define AP 68
#define ATTN_SMEM (4 * 64 * AP * 4)   // 69632 bytes

__global__ __launch_bounds__(256, 3) void attn_kernel(
    const float* __restrict__ qb, const float* __restrict__ kb,
    const float* __restrict__ vb, float* __restrict__ cb) {
    extern __shared__ float smf[];
    float* Qt = smf;                // [64][AP]
    float* Kt = Qt + 64 * AP;
    float* Vs = Kt + 64 * AP;
    float* Pt = Vs + 64 * AP;

    const int tid = threadIdx.x;
    const int tx = tid & 15;
    const int ty = tid >> 4;
    const int t0 = blockIdx.x * 64;
    const int bh = blockIdx.y;
    const int b = bh >> 4;
    const int h = bh & 15;
    const size_t headoff = (size_t)b * D_DIM + (size_t)h * HD_DIM;

    // Load Q transposed + swizzled, pre-scaled by 1/sqrt(64)
    #pragma unroll
    for (int u = 0; u < 4; u++) {
        int idx = u * 256 + tid;          // 0..1023
        int r = idx >> 4;                 // q row 0..63
        int c4 = idx & 15;                // d-group
        float4 v = *(const float4*)&qb[(size_t)(t0 + r) * ROW_STRIDE + headoff + c4 * 4];
        int rs = r ^ (((c4 >> 1) & 3) << 2);
        Qt[(c4 * 4 + 0) * AP + rs] = v.x * 0.125f;
        Qt[(c4 * 4 + 1) * AP + rs] = v.y * 0.125f;
        Qt[(c4 * 4 + 2) * AP + rs] = v.z * 0.125f;
        Qt[(c4 * 4 + 3) * AP + rs] = v.w * 0.125f;
    }

    float m[4], l[4], o[4][4];
    #pragma unroll
    for (int i = 0; i < 4; i++) {
        m[i] = -INFINITY;
        l[i] = 0.0f;
        #pragma unroll
        for (int j = 0; j < 4; j++) o[i][j] = 0.0f;
    }
    __syncthreads();

    for (int j0 = 0; j0 < T_DIM; j0 += 64) {
        // Load K (transposed+swizzled) and V (row-major) tiles
        #pragma unroll
        for (int u = 0; u < 4; u++) {
            int idx = u * 256 + tid;
            int r = idx >> 4;
            int c4 = idx & 15;
            size_t g = (size_t)(j0 + r) * ROW_STRIDE + headoff + c4 * 4;
            float4 kv = *(const float4*)&kb[g];
            float4 vv = *(const float4*)&vb[g];
            int rs = r ^ (((c4 >> 1) & 3) << 2);
            Kt[(c4 * 4 + 0) * AP + rs] = kv.x;
            Kt[(c4 * 4 + 1) * AP + rs] = kv.y;
            Kt[(c4 * 4 + 2) * AP + rs] = kv.z;
            Kt[(c4 * 4 + 3) * AP + rs] = kv.w;
            *(float4*)&Vs[r * AP + c4 * 4] = vv;
        }
        __syncthreads();

        // S = Q K^T, vectorized smem reads
        float s[4][4] = {};
        #pragma unroll 8
        for (int kk = 0; kk < 64; kk++) {
            int sw = ((kk >> 3) & 3) << 2;
            float4 a = *(const float4*)&Qt[kk * AP + ((ty * 4) ^ sw)];
            float4 bv = *(const float4*)&Kt[kk * AP + ((tx * 4) ^ sw)];
            float av[4] = {a.x, a.y, a.z, a.w};
            float bb[4] = {bv.x, bv.y, bv.z, bv.w};
            #pragma unroll
            for (int i = 0; i < 4; i++)
                #pragma unroll
                for (int j = 0; j < 4; j++)
                    s[i][j] += av[i] * bb[j];
        }

        // Online softmax per q-row (16-lane row groups; xor<=8 stays in group)
        #pragma unroll
        for (int i = 0; i < 4; i++) {
            float tm = s[i][0];
            #pragma unroll
            for (int j = 1; j < 4; j++) tm = fmaxf(tm, s[i][j]);
            tm = fmaxf(tm, __shfl_xor_sync(0xffffffffu, tm, 1));
            tm = fmaxf(tm, __shfl_xor_sync(0xffffffffu, tm, 2));
            tm = fmaxf(tm, __shfl_xor_sync(0xffffffffu, tm, 4));
            tm = fmaxf(tm, __shfl_xor_sync(0xffffffffu, tm, 8));

            float mn = fmaxf(m[i], tm);
            float alpha = __expf(m[i] - mn);
            m[i] = mn;

            float ps = 0.0f;
            #pragma unroll
            for (int j = 0; j < 4; j++) {
                s[i][j] = __expf(s[i][j] - mn);
                ps += s[i][j];
            }
            ps += __shfl_xor_sync(0xffffffffu, ps, 1);
            ps += __shfl_xor_sync(0xffffffffu, ps, 2);
            ps += __shfl_xor_sync(0xffffffffu, ps, 4);
            ps += __shfl_xor_sync(0xffffffffu, ps, 8);

            l[i] = l[i] * alpha + ps;
            #pragma unroll
            for (int j = 0; j < 4; j++) o[i][j] *= alpha;
            // store P transposed + swizzled: Pt[kcol][qrow]
            #pragma unroll
            for (int j = 0; j < 4; j++) {
                int c = tx * 4 + j;
                Pt[c * AP + ((ty * 4 + i) ^ (((c >> 3) & 3) << 2))] = s[i][j];
            }
        }
        __syncthreads();

        // O += P V  (vectorized reads of Pt and Vs)
        #pragma unroll 8
        for (int c = 0; c < 64; c++) {
            int sw = ((c >> 3) & 3) << 2;
            float4 p = *(const float4*)&Pt[c * AP + ((ty * 4) ^ sw)];
            float4 v = *(const float4*)&Vs[c * AP + tx * 4];
            float pv[4] = {p.x, p.y, p.z, p.w};
            float vv[4] = {v.x, v.y, v.z, v.w};
            #pragma unroll
            for (int i = 0; i < 4; i++)
                #pragma unroll
                for (int j = 0; j < 4; j++)
                    o[i][j] += pv[i] * vv[j];
        }
        __syncthreads();
    }

    // Normalize and write context as (t, b, h, d)
    #pragma unroll
    for (int i = 0; i < 4; i++) {
        float inv = 1.0f / l[i];
        #pragma unroll
        for (int j = 0; j < 4; j++)
            cb[(size_t)(t0 + ty * 4 + i) * ROW_STRIDE + headoff + tx * 4 + j] =
                o[i][j] * inv;
    }
}

// ---------------------------------------------------------------------------
// Launch
// ---------------------------------------------------------------------------
extern "C" void kernel_launch(void* const* d_in, const int* in_sizes, int n_in,
                              void* d_out, int out_size) {
    const float* query = (const float*)d_in[0];
    const float* key   = (const float*)d_in[1];
    const float* value = (const float*)d_in[2];
    const float* Wq = (const float*)d_in[3];
    const float* bq = (const float*)d_in[4];
    const float* Wk = (const float*)d_in[5];
    const float* bk = (const float*)d_in[6];
    const float* Wv = (const float*)d_in[7];
    const float* bv = (const float*)d_in[8];
    const float* Wo = (const float*)d_in[9];
    const float* bo = (const float*)d_in[10];
    float* out = (float*)d_out;

    float *qb, *kb, *vb, *cb;
    cudaGetSymbolAddress((void**)&qb, g_q);
    cudaGetSymbolAddress((void**)&kb, g_k);
    cudaGetSymbolAddress((void**)&vb, g_v);
    cudaGetSymbolAddress((void**)&cb, g_ctx);

    cudaFuncSetAttribute(attn_kernel,
                         cudaFuncAttributeMaxDynamicSharedMemorySize,
                         ATTN_SMEM);

    dim3 gemm_grid(1024 / BN, M_ROWS / BM);   // (8, 64)
    gemm_bias_kernel<<<gemm_grid, 256>>>(query, Wq, bq, qb);
    gemm_bias_kernel<<<gemm_grid, 256>>>(key,   Wk, bk, kb);
    gemm_bias_kernel<<<gemm_grid, 256>>>(value, Wv, bv, vb);

    dim3 attn_grid(T_DIM / 64, B_DIM * H_DIM);  // (16, 128)
    attn_kernel<<<attn_grid, 256, ATTN_SMEM>>>(qb, kb, vb, cb);

    gemm_bias_kernel<<<gemm_grid, 256>>>(cb, Wo, bo, out);
}

// round 9
// speedup vs baseline: 2.2458x; 1.6868x over previous
#include <cuda_runtime.h>
#include <cuda_bf16.h>
#include <stdint.h>
#include <math.h>

// Problem constants
#define T_DIM 1024
#define B_DIM 8
#define D_DIM 1024
#define H_DIM 16
#define HD_DIM 64
#define M_ROWS (T_DIM * B_DIM)        // 8192
#define ROW_STRIDE (B_DIM * D_DIM)    // 8192 floats between consecutive t

// Scratch buffers (no cudaMalloc allowed)
__device__ float g_q[T_DIM * B_DIM * D_DIM];
__device__ float g_k[T_DIM * B_DIM * D_DIM];
__device__ float g_v[T_DIM * B_DIM * D_DIM];
__device__ float g_ctx[T_DIM * B_DIM * D_DIM];

// ===========================================================================
// Helpers
// ===========================================================================
__device__ __forceinline__ uint32_t smem_u32(const void* p) {
    uint32_t a;
    asm("{ .reg .u64 t; cvta.to.shared.u64 t, %1; cvt.u32.u64 %0, t; }"
        : "=r"(a) : "l"(p));
    return a;
}
#define SW128(o) ((o) ^ (((o) >> 3) & 0x70))

#define LDSM4(r, addr) \
    asm volatile("ldmatrix.sync.aligned.m8n8.x4.shared.b16 {%0,%1,%2,%3}, [%4];" \
        : "=r"((r)[0]), "=r"((r)[1]), "=r"((r)[2]), "=r"((r)[3]) : "r"(addr))

#define MMA_BF16(d, a, b0_, b1_) \
    asm volatile("mma.sync.aligned.m16n8k16.row.col.f32.bf16.bf16.f32 " \
        "{%0,%1,%2,%3}, {%4,%5,%6,%7}, {%8,%9}, {%0,%1,%2,%3};" \
        : "+f"((d)[0]), "+f"((d)[1]), "+f"((d)[2]), "+f"((d)[3]) \
        : "r"((a)[0]), "r"((a)[1]), "r"((a)[2]), "r"((a)[3]), \
          "r"(b0_), "r"(b1_))

__device__ __forceinline__ void sts128(uint32_t addr, uint32_t a, uint32_t b,
                                       uint32_t c, uint32_t d) {
    asm volatile("st.shared.v4.b32 [%0], {%1,%2,%3,%4};"
                 :: "r"(addr), "r"(a), "r"(b), "r"(c), "r"(d) : "memory");
}
// split fp32 pair -> (hi bf16x2 word, lo bf16x2 word)
__device__ __forceinline__ void cvt_pair(float f0, float f1,
                                         uint32_t& hw, uint32_t& lw) {
    __nv_bfloat162 h = __floats2bfloat162_rn(f0, f1);
    float g0 = __bfloat162float(__low2bfloat16(h));
    float g1 = __bfloat162float(__high2bfloat16(h));
    __nv_bfloat162 l = __floats2bfloat162_rn(f0 - g0, f1 - g1);
    hw = *reinterpret_cast<uint32_t*>(&h);
    lw = *reinterpret_cast<uint32_t*>(&l);
}

// ===========================================================================
// Split-bf16 warp-MMA GEMM: C[8192][1024] = A @ W^T + bias (fp32 in/out)
// CTA 128x128, BK=32 fp32/stage. Smem rows are 128B: [hi 32 bf16 | lo 32 bf16],
// SW128-swizzled -> conflict-free ldmatrix. Double-buffered, reg-staged
// prefetch. 8 warps as 2(M) x 4(N); warp tile 64x32; m16n8k16 bf16 HMMA.
// 3 MMA terms per tile: Ah*Bh + Al*Bh + Ah*Bl.
// ===========================================================================
#define G_STAGE 32768                    // As 16KB + Bs 16KB
#define GEMM_SMEM (2 * G_STAGE)          // 65536

__global__ __launch_bounds__(256, 1) void gemm_tc_kernel(
    const float* __restrict__ A, const float* __restrict__ W,
    const float* __restrict__ bias, float* __restrict__ C) {
    extern __shared__ char smem[];
    const uint32_t sb = smem_u32(smem);

    const int tid = threadIdx.x;
    const int wid = tid >> 5;
    const int lane = tid & 31;
    const int warp_m = wid >> 2;          // 0..1 -> m offset *64
    const int warp_n = wid & 3;           // 0..3 -> n offset *32
    const int row0 = blockIdx.y * 128;
    const int col0 = blockIdx.x * 128;

    // ldmatrix lane geometry
    const int grp = lane >> 3, rin = lane & 7;
    const int a_mrow = ((grp & 1) << 3) + rin;   // A: grp0 m0-7@k0, grp1 m8-15@k0, grp2 m0-7@+16, grp3 m8-15@+16
    const int a_kb   = (grp >> 1) << 4;
    const int b_nrow = ((grp >> 1) << 3) + rin;  // B: grp0 n0-7@k0, grp1 n0-7@+16, grp2 n8-15@k0, grp3 n8-15@+16
    const int b_kb   = (grp & 1) << 4;

    // loader geometry: flat = tid + g*256 -> r = flat>>2 (0..127), c8 = flat&3
    const int r_ld = tid >> 2;
    const int c8 = tid & 3;
    const float* Abase = A + (size_t)(row0 + r_ld) * 1024 + c8 * 8;
    const float* Wbase = W + (size_t)(col0 + r_ld) * 1024 + c8 * 8;

    float acc[4][4][4];
    #pragma unroll
    for (int i = 0; i < 4; i++)
        #pragma unroll
        for (int j = 0; j < 4; j++)
            #pragma unroll
            for (int k = 0; k < 4; k++) acc[i][j][k] = 0.0f;

    float4 ra[4], rb[4];
    // prologue: load + store stage 0
    #pragma unroll
    for (int g = 0; g < 2; g++) {
        const float* pa = Abase + (size_t)g * 64 * 1024;
        const float* pw = Wbase + (size_t)g * 64 * 1024;
        ra[2 * g] = *(const float4*)pa;  ra[2 * g + 1] = *(const float4*)(pa + 4);
        rb[2 * g] = *(const float4*)pw;  rb[2 * g + 1] = *(const float4*)(pw + 4);
    }
    #pragma unroll
    for (int g = 0; g < 2; g++) {
        int r = r_ld + g * 64;
        uint32_t off = r * 128 + c8 * 16;
        uint32_t h0, h1, h2, h3, l0, l1, l2, l3;
        cvt_pair(ra[2*g].x, ra[2*g].y, h0, l0);
        cvt_pair(ra[2*g].z, ra[2*g].w, h1, l1);
        cvt_pair(ra[2*g+1].x, ra[2*g+1].y, h2, l2);
        cvt_pair(ra[2*g+1].z, ra[2*g+1].w, h3, l3);
        sts128(sb + SW128(off), h0, h1, h2, h3);
        sts128(sb + SW128(off + 64), l0, l1, l2, l3);
        cvt_pair(rb[2*g].x, rb[2*g].y, h0, l0);
        cvt_pair(rb[2*g].z, rb[2*g].w, h1, l1);
        cvt_pair(rb[2*g+1].x, rb[2*g+1].y, h2, l2);
        cvt_pair(rb[2*g+1].z, rb[2*g+1].w, h3, l3);
        sts128(sb + 16384 + SW128(off), h0, h1, h2, h3);
        sts128(sb + 16384 + SW128(off + 64), l0, l1, l2, l3);
    }
    __syncthreads();

    #pragma unroll 1
    for (int s = 0; s < 32; s++) {
        const int buf = s & 1;
        const bool next = (s + 1) < 32;
        if (next) {
            const int kb = (s + 1) * 32;
            #pragma unroll
            for (int g = 0; g < 2; g++) {
                const float* pa = Abase + (size_t)g * 64 * 1024 + kb;
                const float* pw = Wbase + (size_t)g * 64 * 1024 + kb;
                ra[2 * g] = *(const float4*)pa;  ra[2 * g + 1] = *(const float4*)(pa + 4);
                rb[2 * g] = *(const float4*)pw;  rb[2 * g + 1] = *(const float4*)(pw + 4);
            }
        }

        // ---- MMA on stage buf ----
        const uint32_t AsB = sb + buf * G_STAGE;
        const uint32_t BsB = AsB + 16384;
        #pragma unroll
        for (int ks = 0; ks < 2; ks++) {
            uint32_t ah[4][4], al[4][4], bh[2][4], bl[2][4];
            #pragma unroll
            for (int mt = 0; mt < 4; mt++) {
                int row = warp_m * 64 + mt * 16 + a_mrow;
                uint32_t off = row * 128 + ks * 32 + a_kb;
                LDSM4(ah[mt], AsB + SW128(off));
                LDSM4(al[mt], AsB + SW128(off + 64));
            }
            #pragma unroll
            for (int np = 0; np < 2; np++) {
                int row = warp_n * 32 + np * 16 + b_nrow;
                uint32_t off = row * 128 + ks * 32 + b_kb;
                LDSM4(bh[np], BsB + SW128(off));
                LDSM4(bl[np], BsB + SW128(off + 64));
            }
            #pragma unroll
            for (int mt = 0; mt < 4; mt++)
                #pragma unroll
                for (int np = 0; np < 2; np++)
                    #pragma unroll
                    for (int sub = 0; sub < 2; sub++) {
                        float* d = acc[mt][np * 2 + sub];
                        MMA_BF16(d, ah[mt], bh[np][sub * 2], bh[np][sub * 2 + 1]);
                        MMA_BF16(d, al[mt], bh[np][sub * 2], bh[np][sub * 2 + 1]);
                        MMA_BF16(d, ah[mt], bl[np][sub * 2], bl[np][sub * 2 + 1]);
                    }
        }

        if (next) {
            const uint32_t AsN = sb + (buf ^ 1) * G_STAGE;
            #pragma unroll
            for (int g = 0; g < 2; g++) {
                int r = r_ld + g * 64;
                uint32_t off = r * 128 + c8 * 16;
                uint32_t h0, h1, h2, h3, l0, l1, l2, l3;
                cvt_pair(ra[2*g].x, ra[2*g].y, h0, l0);
                cvt_pair(ra[2*g].z, ra[2*g].w, h1, l1);
                cvt_pair(ra[2*g+1].x, ra[2*g+1].y, h2, l2);
                cvt_pair(ra[2*g+1].z, ra[2*g+1].w, h3, l3);
                sts128(AsN + SW128(off), h0, h1, h2, h3);
                sts128(AsN + SW128(off + 64), l0, l1, l2, l3);
                cvt_pair(rb[2*g].x, rb[2*g].y, h0, l0);
                cvt_pair(rb[2*g].z, rb[2*g].w, h1, l1);
                cvt_pair(rb[2*g+1].x, rb[2*g+1].y, h2, l2);
                cvt_pair(rb[2*g+1].z, rb[2*g+1].w, h3, l3);
                sts128(AsN + 16384 + SW128(off), h0, h1, h2, h3);
                sts128(AsN + 16384 + SW128(off + 64), l0, l1, l2, l3);
            }
        }
        __syncthreads();
    }

    // Epilogue: frag layout c0,c1 = (m = lane/4, n = 2*(lane%4)+{0,1}); c2,c3 m+8
    #pragma unroll
    for (int mt = 0; mt < 4; mt++) {
        int rg = row0 + warp_m * 64 + mt * 16 + (lane >> 2);
        #pragma unroll
        for (int nt = 0; nt < 4; nt++) {
            int cg = col0 + warp_n * 32 + nt * 8 + (lane & 3) * 2;
            float b0 = __ldg(&bias[cg]), b1 = __ldg(&bias[cg + 1]);
            float2 v0 = make_float2(acc[mt][nt][0] + b0, acc[mt][nt][1] + b1);
            float2 v1 = make_float2(acc[mt][nt][2] + b0, acc[mt][nt][3] + b1);
            *(float2*)&C[(size_t)rg * 1024 + cg] = v0;
            *(float2*)&C[(size_t)(rg + 8) * 1024 + cg] = v1;
        }
    }
}

// ===========================================================================
// Attention (known-good R1): flash-style fp32, 64x64 tiles, 256 threads
// ===========================================================================
#define AP 68
#define ATTN_SMEM (4 * 64 * AP * 4)

__global__ __launch_bounds__(256, 3) void attn_kernel(
    const float* __restrict__ qb, const float* __restrict__ kb,
    const float* __restrict__ vb, float* __restrict__ cb) {
    extern __shared__ float smf[];
    float* Qt = smf;
    float* Kt = Qt + 64 * AP;
    float* Vs = Kt + 64 * AP;
    float* Pt = Vs + 64 * AP;

    const int tid = threadIdx.x;
    const int tx = tid & 15;
    const int ty = tid >> 4;
    const int t0 = blockIdx.x * 64;
    const int bh = blockIdx.y;
    const int b = bh >> 4;
    const int h = bh & 15;
    const size_t headoff = (size_t)b * D_DIM + (size_t)h * HD_DIM;

    #pragma unroll
    for (int u = 0; u < 4; u++) {
        int idx = u * 256 + tid;
        int r = idx >> 4;
        int c4 = idx & 15;
        float4 v = *(const float4*)&qb[(size_t)(t0 + r) * ROW_STRIDE + headoff + c4 * 4];
        int rs = r ^ (((c4 >> 1) & 3) << 2);
        Qt[(c4 * 4 + 0) * AP + rs] = v.x * 0.125f;
        Qt[(c4 * 4 + 1) * AP + rs] = v.y * 0.125f;
        Qt[(c4 * 4 + 2) * AP + rs] = v.z * 0.125f;
        Qt[(c4 * 4 + 3) * AP + rs] = v.w * 0.125f;
    }

    float m[4], l[4], o[4][4];
    #pragma unroll
    for (int i = 0; i < 4; i++) {
        m[i] = -INFINITY;
        l[i] = 0.0f;
        #pragma unroll
        for (int j = 0; j < 4; j++) o[i][j] = 0.0f;
    }
    __syncthreads();

    for (int j0 = 0; j0 < T_DIM; j0 += 64) {
        #pragma unroll
        for (int u = 0; u < 4; u++) {
            int idx = u * 256 + tid;
            int r = idx >> 4;
            int c4 = idx & 15;
            size_t g = (size_t)(j0 + r) * ROW_STRIDE + headoff + c4 * 4;
            float4 kv = *(const float4*)&kb[g];
            float4 vv = *(const float4*)&vb[g];
            int rs = r ^ (((c4 >> 1) & 3) << 2);
            Kt[(c4 * 4 + 0) * AP + rs] = kv.x;
            Kt[(c4 * 4 + 1) * AP + rs] = kv.y;
            Kt[(c4 * 4 + 2) * AP + rs] = kv.z;
            Kt[(c4 * 4 + 3) * AP + rs] = kv.w;
            *(float4*)&Vs[r * AP + c4 * 4] = vv;
        }
        __syncthreads();

        float s[4][4] = {};
        #pragma unroll 8
        for (int kk = 0; kk < 64; kk++) {
            int sw = ((kk >> 3) & 3) << 2;
            float4 a = *(const float4*)&Qt[kk * AP + ((ty * 4) ^ sw)];
            float4 bv = *(const float4*)&Kt[kk * AP + ((tx * 4) ^ sw)];
            float av[4] = {a.x, a.y, a.z, a.w};
            float bb[4] = {bv.x, bv.y, bv.z, bv.w};
            #pragma unroll
            for (int i = 0; i < 4; i++)
                #pragma unroll
                for (int j = 0; j < 4; j++)
                    s[i][j] += av[i] * bb[j];
        }

        #pragma unroll
        for (int i = 0; i < 4; i++) {
            float tm = s[i][0];
            #pragma unroll
            for (int j = 1; j < 4; j++) tm = fmaxf(tm, s[i][j]);
            tm = fmaxf(tm, __shfl_xor_sync(0xffffffffu, tm, 1));
            tm = fmaxf(tm, __shfl_xor_sync(0xffffffffu, tm, 2));
            tm = fmaxf(tm, __shfl_xor_sync(0xffffffffu, tm, 4));
            tm = fmaxf(tm, __shfl_xor_sync(0xffffffffu, tm, 8));

            float mn = fmaxf(m[i], tm);
            float alpha = __expf(m[i] - mn);
            m[i] = mn;

            float ps = 0.0f;
            #pragma unroll
            for (int j = 0; j < 4; j++) {
                s[i][j] = __expf(s[i][j] - mn);
                ps += s[i][j];
            }
            ps += __shfl_xor_sync(0xffffffffu, ps, 1);
            ps += __shfl_xor_sync(0xffffffffu, ps, 2);
            ps += __shfl_xor_sync(0xffffffffu, ps, 4);
            ps += __shfl_xor_sync(0xffffffffu, ps, 8);

            l[i] = l[i] * alpha + ps;
            #pragma unroll
            for (int j = 0; j < 4; j++) o[i][j] *= alpha;
            #pragma unroll
            for (int j = 0; j < 4; j++) {
                int c = tx * 4 + j;
                Pt[c * AP + ((ty * 4 + i) ^ (((c >> 3) & 3) << 2))] = s[i][j];
            }
        }
        __syncthreads();

        #pragma unroll 8
        for (int c = 0; c < 64; c++) {
            int sw = ((c >> 3) & 3) << 2;
            float4 p = *(const float4*)&Pt[c * AP + ((ty * 4) ^ sw)];
            float4 v = *(const float4*)&Vs[c * AP + tx * 4];
            float pv[4] = {p.x, p.y, p.z, p.w};
            float vv[4] = {v.x, v.y, v.z, v.w};
            #pragma unroll
            for (int i = 0; i < 4; i++)
                #pragma unroll
                for (int j = 0; j < 4; j++)
                    o[i][j] += pv[i] * vv[j];
        }
        __syncthreads();
    }

    #pragma unroll
    for (int i = 0; i < 4; i++) {
        float inv = 1.0f / l[i];
        #pragma unroll
        for (int j = 0; j < 4; j++)
            cb[(size_t)(t0 + ty * 4 + i) * ROW_STRIDE + headoff + tx * 4 + j] =
                o[i][j] * inv;
    }
}

// ===========================================================================
// Launch
// ===========================================================================
extern "C" void kernel_launch(void* const* d_in, const int* in_sizes, int n_in,
                              void* d_out, int out_size) {
    const float* query = (const float*)d_in[0];
    const float* key   = (const float*)d_in[1];
    const float* value = (const float*)d_in[2];
    const float* Wq = (const float*)d_in[3];
    const float* bq = (const float*)d_in[4];
    const float* Wk = (const float*)d_in[5];
    const float* bk = (const float*)d_in[6];
    const float* Wv = (const float*)d_in[7];
    const float* bv = (const float*)d_in[8];
    const float* Wo = (const float*)d_in[9];
    const float* bo = (const float*)d_in[10];
    float* out = (float*)d_out;

    float *qb, *kb, *vb, *cb;
    cudaGetSymbolAddress((void**)&qb, g_q);
    cudaGetSymbolAddress((void**)&kb, g_k);
    cudaGetSymbolAddress((void**)&vb, g_v);
    cudaGetSymbolAddress((void**)&cb, g_ctx);

    cudaFuncSetAttribute(gemm_tc_kernel,
                         cudaFuncAttributeMaxDynamicSharedMemorySize, GEMM_SMEM);
    cudaFuncSetAttribute(attn_kernel,
                         cudaFuncAttributeMaxDynamicSharedMemorySize, ATTN_SMEM);

    dim3 gemm_grid(1024 / 128, M_ROWS / 128);   // (8, 64) = 512 CTAs
    gemm_tc_kernel<<<gemm_grid, 256, GEMM_SMEM>>>(query, Wq, bq, qb);
    gemm_tc_kernel<<<gemm_grid, 256, GEMM_SMEM>>>(key,   Wk, bk, kb);
    gemm_tc_kernel<<<gemm_grid, 256, GEMM_SMEM>>>(value, Wv, bv, vb);

    dim3 attn_grid(T_DIM / 64, B_DIM * H_DIM);  // (16, 128)
    attn_kernel<<<attn_grid, 256, ATTN_SMEM>>>(qb, kb, vb, cb);

    gemm_tc_kernel<<<gemm_grid, 256, GEMM_SMEM>>>(cb, Wo, bo, out);
}

// round 10
// speedup vs baseline: 3.8019x; 1.6929x over previous
#include <cuda_runtime.h>
#include <cuda_bf16.h>
#include <stdint.h>
#include <math.h>

// Problem constants
#define T_DIM 1024
#define B_DIM 8
#define D_DIM 1024
#define H_DIM 16
#define HD_DIM 64
#define M_ROWS (T_DIM * B_DIM)        // 8192

// Scratch: bf16 hi/lo planes [b*16+h][t][64] (16 MB each) + fp32 ctx
#define PLANE_ELEMS (128 * 1024 * 64)
__device__ __nv_bfloat16 g_qh[PLANE_ELEMS], g_ql[PLANE_ELEMS];
__device__ __nv_bfloat16 g_kh[PLANE_ELEMS], g_kl[PLANE_ELEMS];
__device__ __nv_bfloat16 g_vh[PLANE_ELEMS], g_vl[PLANE_ELEMS];
__device__ float g_ctx[M_ROWS * D_DIM];

// ===========================================================================
// Helpers
// ===========================================================================
__device__ __forceinline__ uint32_t smem_u32(const void* p) {
    uint32_t a;
    asm("{ .reg .u64 t; cvta.to.shared.u64 t, %1; cvt.u32.u64 %0, t; }"
        : "=r"(a) : "l"(p));
    return a;
}
#define SW128(o) ((o) ^ (((o) >> 3) & 0x70))

#define LDSM4(r, addr) \
    asm volatile("ldmatrix.sync.aligned.m8n8.x4.shared.b16 {%0,%1,%2,%3}, [%4];" \
        : "=r"((r)[0]), "=r"((r)[1]), "=r"((r)[2]), "=r"((r)[3]) : "r"(addr))

#define LDSM4T(r, addr) \
    asm volatile("ldmatrix.sync.aligned.m8n8.x4.trans.shared.b16 {%0,%1,%2,%3}, [%4];" \
        : "=r"((r)[0]), "=r"((r)[1]), "=r"((r)[2]), "=r"((r)[3]) : "r"(addr))

#define MMA_BF16(d, a, b0_, b1_) \
    asm volatile("mma.sync.aligned.m16n8k16.row.col.f32.bf16.bf16.f32 " \
        "{%0,%1,%2,%3}, {%4,%5,%6,%7}, {%8,%9}, {%0,%1,%2,%3};" \
        : "+f"((d)[0]), "+f"((d)[1]), "+f"((d)[2]), "+f"((d)[3]) \
        : "r"((a)[0]), "r"((a)[1]), "r"((a)[2]), "r"((a)[3]), \
          "r"(b0_), "r"(b1_))

__device__ __forceinline__ void sts128(uint32_t addr, uint32_t a, uint32_t b,
                                       uint32_t c, uint32_t d) {
    asm volatile("st.shared.v4.b32 [%0], {%1,%2,%3,%4};"
                 :: "r"(addr), "r"(a), "r"(b), "r"(c), "r"(d) : "memory");
}
// split fp32 pair -> (hi bf16x2 word, lo bf16x2 word)
__device__ __forceinline__ void cvt_pair(float f0, float f1,
                                         uint32_t& hw, uint32_t& lw) {
    __nv_bfloat162 h = __floats2bfloat162_rn(f0, f1);
    float g0 = __bfloat162float(__low2bfloat16(h));
    float g1 = __bfloat162float(__high2bfloat16(h));
    __nv_bfloat162 l = __floats2bfloat162_rn(f0 - g0, f1 - g1);
    hw = *reinterpret_cast<uint32_t*>(&h);
    lw = *reinterpret_cast<uint32_t*>(&l);
}

// ===========================================================================
// Split-bf16 warp-MMA GEMM: out = A[8192][1024] @ W^T + bias.
// Epilogue modes: fp32 row-major C (Ph==nullptr), or scaled hi/lo bf16
// head-major planes [b*16+h][t][64].
// ===========================================================================
#define G_STAGE 32768
#define GEMM_SMEM (2 * G_STAGE)

__global__ __launch_bounds__(256, 1) void gemm_tc_kernel(
    const float* __restrict__ A, const float* __restrict__ W,
    const float* __restrict__ bias, float* __restrict__ C,
    __nv_bfloat16* __restrict__ Ph, __nv_bfloat16* __restrict__ Pl,
    float scale) {
    extern __shared__ char smem[];
    const uint32_t sb = smem_u32(smem);

    const int tid = threadIdx.x;
    const int wid = tid >> 5;
    const int lane = tid & 31;
    const int warp_m = wid >> 2;
    const int warp_n = wid & 3;
    const int row0 = blockIdx.y * 128;
    const int col0 = blockIdx.x * 128;

    const int grp = lane >> 3, rin = lane & 7;
    const int a_mrow = ((grp & 1) << 3) + rin;
    const int a_kb   = (grp >> 1) << 4;
    const int b_nrow = ((grp >> 1) << 3) + rin;
    const int b_kb   = (grp & 1) << 4;

    const int r_ld = tid >> 2;
    const int c8 = tid & 3;
    const float* Abase = A + (size_t)(row0 + r_ld) * 1024 + c8 * 8;
    const float* Wbase = W + (size_t)(col0 + r_ld) * 1024 + c8 * 8;

    float acc[4][4][4];
    #pragma unroll
    for (int i = 0; i < 4; i++)
        #pragma unroll
        for (int j = 0; j < 4; j++)
            #pragma unroll
            for (int k = 0; k < 4; k++) acc[i][j][k] = 0.0f;

    float4 ra[4], rb[4];
    #pragma unroll
    for (int g = 0; g < 2; g++) {
        const float* pa = Abase + (size_t)g * 64 * 1024;
        const float* pw = Wbase + (size_t)g * 64 * 1024;
        ra[2 * g] = *(const float4*)pa;  ra[2 * g + 1] = *(const float4*)(pa + 4);
        rb[2 * g] = *(const float4*)pw;  rb[2 * g + 1] = *(const float4*)(pw + 4);
    }
    #pragma unroll
    for (int g = 0; g < 2; g++) {
        int r = r_ld + g * 64;
        uint32_t off = r * 128 + c8 * 16;
        uint32_t h0, h1, h2, h3, l0, l1, l2, l3;
        cvt_pair(ra[2*g].x, ra[2*g].y, h0, l0);
        cvt_pair(ra[2*g].z, ra[2*g].w, h1, l1);
        cvt_pair(ra[2*g+1].x, ra[2*g+1].y, h2, l2);
        cvt_pair(ra[2*g+1].z, ra[2*g+1].w, h3, l3);
        sts128(sb + SW128(off), h0, h1, h2, h3);
        sts128(sb + SW128(off + 64), l0, l1, l2, l3);
        cvt_pair(rb[2*g].x, rb[2*g].y, h0, l0);
        cvt_pair(rb[2*g].z, rb[2*g].w, h1, l1);
        cvt_pair(rb[2*g+1].x, rb[2*g+1].y, h2, l2);
        cvt_pair(rb[2*g+1].z, rb[2*g+1].w, h3, l3);
        sts128(sb + 16384 + SW128(off), h0, h1, h2, h3);
        sts128(sb + 16384 + SW128(off + 64), l0, l1, l2, l3);
    }
    __syncthreads();

    #pragma unroll 1
    for (int s = 0; s < 32; s++) {
        const int buf = s & 1;
        const bool next = (s + 1) < 32;
        if (next) {
            const int kb = (s + 1) * 32;
            #pragma unroll
            for (int g = 0; g < 2; g++) {
                const float* pa = Abase + (size_t)g * 64 * 1024 + kb;
                const float* pw = Wbase + (size_t)g * 64 * 1024 + kb;
                ra[2 * g] = *(const float4*)pa;  ra[2 * g + 1] = *(const float4*)(pa + 4);
                rb[2 * g] = *(const float4*)pw;  rb[2 * g + 1] = *(const float4*)(pw + 4);
            }
        }

        const uint32_t AsB = sb + buf * G_STAGE;
        const uint32_t BsB = AsB + 16384;
        #pragma unroll
        for (int ks = 0; ks < 2; ks++) {
            uint32_t ah[4][4], al[4][4], bh[2][4], bl[2][4];
            #pragma unroll
            for (int mt = 0; mt < 4; mt++) {
                int row = warp_m * 64 + mt * 16 + a_mrow;
                uint32_t off = row * 128 + ks * 32 + a_kb;
                LDSM4(ah[mt], AsB + SW128(off));
                LDSM4(al[mt], AsB + SW128(off + 64));
            }
            #pragma unroll
            for (int np = 0; np < 2; np++) {
                int row = warp_n * 32 + np * 16 + b_nrow;
                uint32_t off = row * 128 + ks * 32 + b_kb;
                LDSM4(bh[np], BsB + SW128(off));
                LDSM4(bl[np], BsB + SW128(off + 64));
            }
            #pragma unroll
            for (int mt = 0; mt < 4; mt++)
                #pragma unroll
                for (int np = 0; np < 2; np++)
                    #pragma unroll
                    for (int sub = 0; sub < 2; sub++) {
                        float* d = acc[mt][np * 2 + sub];
                        MMA_BF16(d, ah[mt], bh[np][sub * 2], bh[np][sub * 2 + 1]);
                        MMA_BF16(d, al[mt], bh[np][sub * 2], bh[np][sub * 2 + 1]);
                        MMA_BF16(d, ah[mt], bl[np][sub * 2], bl[np][sub * 2 + 1]);
                    }
        }

        if (next) {
            const uint32_t AsN = sb + (buf ^ 1) * G_STAGE;
            #pragma unroll
            for (int g = 0; g < 2; g++) {
                int r = r_ld + g * 64;
                uint32_t off = r * 128 + c8 * 16;
                uint32_t h0, h1, h2, h3, l0, l1, l2, l3;
                cvt_pair(ra[2*g].x, ra[2*g].y, h0, l0);
                cvt_pair(ra[2*g].z, ra[2*g].w, h1, l1);
                cvt_pair(ra[2*g+1].x, ra[2*g+1].y, h2, l2);
                cvt_pair(ra[2*g+1].z, ra[2*g+1].w, h3, l3);
                sts128(AsN + SW128(off), h0, h1, h2, h3);
                sts128(AsN + SW128(off + 64), l0, l1, l2, l3);
                cvt_pair(rb[2*g].x, rb[2*g].y, h0, l0);
                cvt_pair(rb[2*g].z, rb[2*g].w, h1, l1);
                cvt_pair(rb[2*g+1].x, rb[2*g+1].y, h2, l2);
                cvt_pair(rb[2*g+1].z, rb[2*g+1].w, h3, l3);
                sts128(AsN + 16384 + SW128(off), h0, h1, h2, h3);
                sts128(AsN + 16384 + SW128(off + 64), l0, l1, l2, l3);
            }
        }
        __syncthreads();
    }

    // Epilogue
    if (Ph == nullptr) {
        #pragma unroll
        for (int mt = 0; mt < 4; mt++) {
            int rg = row0 + warp_m * 64 + mt * 16 + (lane >> 2);
            #pragma unroll
            for (int nt = 0; nt < 4; nt++) {
                int cg = col0 + warp_n * 32 + nt * 8 + (lane & 3) * 2;
                float b0 = __ldg(&bias[cg]), b1 = __ldg(&bias[cg + 1]);
                float2 v0 = make_float2(acc[mt][nt][0] + b0, acc[mt][nt][1] + b1);
                float2 v1 = make_float2(acc[mt][nt][2] + b0, acc[mt][nt][3] + b1);
                *(float2*)&C[(size_t)rg * 1024 + cg] = v0;
                *(float2*)&C[(size_t)(rg + 8) * 1024 + cg] = v1;
            }
        }
    } else {
        // write hi/lo bf16 planes [b*16+h][t][64], scaled
        #pragma unroll
        for (int mt = 0; mt < 4; mt++) {
            int rg = row0 + warp_m * 64 + mt * 16 + (lane >> 2);
            int t = rg >> 3, bb = rg & 7;
            #pragma unroll
            for (int nt = 0; nt < 4; nt++) {
                int cg = col0 + warp_n * 32 + nt * 8 + (lane & 3) * 2;
                int hh = cg >> 6, hd = cg & 63;
                size_t pb = ((size_t)(bb * 16 + hh)) * 65536 + (size_t)t * 64 + hd;
                float b0 = __ldg(&bias[cg]), b1 = __ldg(&bias[cg + 1]);
                uint32_t hw, lw;
                cvt_pair((acc[mt][nt][0] + b0) * scale,
                         (acc[mt][nt][1] + b1) * scale, hw, lw);
                *(uint32_t*)&Ph[pb] = hw;
                *(uint32_t*)&Pl[pb] = lw;
                cvt_pair((acc[mt][nt][2] + b0) * scale,
                         (acc[mt][nt][3] + b1) * scale, hw, lw);
                *(uint32_t*)&Ph[pb + 64] = hw;      // rg+8 -> t+1
                *(uint32_t*)&Pl[pb + 64] = lw;
            }
        }
    }
}

// ===========================================================================
// Tensor-core flash attention, split-bf16 3-term on both matmuls.
// CTA = 128 q-rows x 1 head, 8 warps x 16 rows. K/V tiles of 128.
// S C-frags repacked in-register to A-frags for PV. ctx written fp32 in
// GEMM-A layout [t*8+b][1024].
// ===========================================================================
#define ATTN_SMEM 98304   // 6 planes x 16 KB

__global__ __launch_bounds__(256, 1) void attn_tc_kernel(
    const __nv_bfloat16* __restrict__ qh, const __nv_bfloat16* __restrict__ ql,
    const __nv_bfloat16* __restrict__ kh, const __nv_bfloat16* __restrict__ kl,
    const __nv_bfloat16* __restrict__ vh, const __nv_bfloat16* __restrict__ vl,
    float* __restrict__ ctx) {
    extern __shared__ char smem[];
    const uint32_t sb = smem_u32(smem);
    const int tid = threadIdx.x, wid = tid >> 5, lane = tid & 31;
    const int grp = lane >> 3, rin = lane & 7;
    const int head = blockIdx.y;
    const int q0 = blockIdx.x * 128;
    const size_t hbase = (size_t)head * 65536;

    enum { QH = 0, QL = 16384, KH = 32768, KL = 49152, VH = 65536, VL = 81920 };

    // Load Q hi/lo tile (contiguous 16 KB each) into swizzled smem
    {
        const uint4* sh = (const uint4*)(qh + hbase + (size_t)q0 * 64);
        const uint4* sl = (const uint4*)(ql + hbase + (size_t)q0 * 64);
        #pragma unroll
        for (int i = 0; i < 4; i++) {
            int c = tid + i * 256;
            uint32_t d = SW128(c * 16);
            uint4 a = sh[c]; sts128(sb + QH + d, a.x, a.y, a.z, a.w);
            uint4 b = sl[c]; sts128(sb + QL + d, b.x, b.y, b.z, b.w);
        }
    }
    __syncthreads();

    // Resident Q A-frags
    const int a_row = wid * 16 + ((grp & 1) << 3) + rin;
    const int a_kb = (grp >> 1) << 4;
    uint32_t qfh[4][4], qfl[4][4];
    #pragma unroll
    for (int ks = 0; ks < 4; ks++) {
        uint32_t off = a_row * 128 + ks * 32 + a_kb;
        LDSM4(qfh[ks], sb + QH + SW128(off));
        LDSM4(qfl[ks], sb + QL + SW128(off));
    }

    const int b_rowb = ((grp >> 1) << 3) + rin;   // + nb*16
    const int b_kb = (grp & 1) << 4;
    const int v_rowb = ((grp & 1) << 3) + rin;    // + ksv*16
    const int v_cb = (grp >> 1) << 4;

    float sc[16][4];
    float oacc[8][4];
    #pragma unroll
    for (int i = 0; i < 8; i++)
        #pragma unroll
        for (int j = 0; j < 4; j++) oacc[i][j] = 0.0f;
    float m1 = -INFINITY, m2 = -INFINITY, l1 = 0.0f, l2 = 0.0f;

    #pragma unroll 1
    for (int kt = 0; kt < 8; kt++) {
        __syncthreads();
        {
            size_t tb = hbase + (size_t)kt * 128 * 64;
            const uint4* skh = (const uint4*)(kh + tb);
            const uint4* skl = (const uint4*)(kl + tb);
            const uint4* svh = (const uint4*)(vh + tb);
            const uint4* svl = (const uint4*)(vl + tb);
            #pragma unroll
            for (int i = 0; i < 4; i++) {
                int c = tid + i * 256;
                uint32_t d = SW128(c * 16);
                uint4 x;
                x = skh[c]; sts128(sb + KH + d, x.x, x.y, x.z, x.w);
                x = skl[c]; sts128(sb + KL + d, x.x, x.y, x.z, x.w);
                x = svh[c]; sts128(sb + VH + d, x.x, x.y, x.z, x.w);
                x = svl[c]; sts128(sb + VL + d, x.x, x.y, x.z, x.w);
            }
        }
        __syncthreads();

        // ---- S = Q K^T ----
        #pragma unroll
        for (int j = 0; j < 16; j++)
            #pragma unroll
            for (int c = 0; c < 4; c++) sc[j][c] = 0.0f;
        #pragma unroll
        for (int ks = 0; ks < 4; ks++) {
            #pragma unroll
            for (int nb = 0; nb < 8; nb++) {
                uint32_t kfh[4], kfl[4];
                uint32_t off = (nb * 16 + b_rowb) * 128 + ks * 32 + b_kb;
                LDSM4(kfh, sb + KH + SW128(off));
                LDSM4(kfl, sb + KL + SW128(off));
                #pragma unroll
                for (int sub = 0; sub < 2; sub++) {
                    float* d = sc[nb * 2 + sub];
                    MMA_BF16(d, qfh[ks], kfh[sub * 2], kfh[sub * 2 + 1]);
                    MMA_BF16(d, qfl[ks], kfh[sub * 2], kfh[sub * 2 + 1]);
                    MMA_BF16(d, qfh[ks], kfl[sub * 2], kfl[sub * 2 + 1]);
                }
            }
        }

        // ---- online softmax (rows r1=lane>>2, r2=r1+8; quad-reduce) ----
        float tm1 = -INFINITY, tm2 = -INFINITY;
        #pragma unroll
        for (int j = 0; j < 16; j++) {
            tm1 = fmaxf(tm1, fmaxf(sc[j][0], sc[j][1]));
            tm2 = fmaxf(tm2, fmaxf(sc[j][2], sc[j][3]));
        }
        tm1 = fmaxf(tm1, __shfl_xor_sync(0xffffffffu, tm1, 1));
        tm1 = fmaxf(tm1, __shfl_xor_sync(0xffffffffu, tm1, 2));
        tm2 = fmaxf(tm2, __shfl_xor_sync(0xffffffffu, tm2, 1));
        tm2 = fmaxf(tm2, __shfl_xor_sync(0xffffffffu, tm2, 2));

        float mn1 = fmaxf(m1, tm1), mn2 = fmaxf(m2, tm2);
        float al1 = __expf(m1 - mn1), al2 = __expf(m2 - mn2);
        m1 = mn1; m2 = mn2;

        float s1 = 0.0f, s2 = 0.0f;
        #pragma unroll
        for (int j = 0; j < 16; j++) {
            sc[j][0] = __expf(sc[j][0] - mn1);
            sc[j][1] = __expf(sc[j][1] - mn1);
            s1 += sc[j][0] + sc[j][1];
            sc[j][2] = __expf(sc[j][2] - mn2);
            sc[j][3] = __expf(sc[j][3] - mn2);
            s2 += sc[j][2] + sc[j][3];
        }
        s1 += __shfl_xor_sync(0xffffffffu, s1, 1);
        s1 += __shfl_xor_sync(0xffffffffu, s1, 2);
        s2 += __shfl_xor_sync(0xffffffffu, s2, 1);
        s2 += __shfl_xor_sync(0xffffffffu, s2, 2);
        l1 = l1 * al1 + s1;
        l2 = l2 * al2 + s2;
        #pragma unroll
        for (int nb = 0; nb < 8; nb++) {
            oacc[nb][0] *= al1; oacc[nb][1] *= al1;
            oacc[nb][2] *= al2; oacc[nb][3] *= al2;
        }

        // ---- O += P V ----
        #pragma unroll
        for (int ksv = 0; ksv < 8; ksv++) {
            uint32_t pah[4], pal[4];
            const int j0 = 2 * ksv, j1 = j0 + 1;
            cvt_pair(sc[j0][0], sc[j0][1], pah[0], pal[0]);
            cvt_pair(sc[j0][2], sc[j0][3], pah[1], pal[1]);
            cvt_pair(sc[j1][0], sc[j1][1], pah[2], pal[2]);
            cvt_pair(sc[j1][2], sc[j1][3], pah[3], pal[3]);
            #pragma unroll
            for (int nv = 0; nv < 4; nv++) {
                uint32_t vfh[4], vfl[4];
                uint32_t off = (ksv * 16 + v_rowb) * 128 + nv * 32 + v_cb;
                LDSM4T(vfh, sb + VH + SW128(off));
                LDSM4T(vfl, sb + VL + SW128(off));
                #pragma unroll
                for (int sub = 0; sub < 2; sub++) {
                    float* d = oacc[nv * 2 + sub];
                    MMA_BF16(d, pah, vfh[sub * 2], vfh[sub * 2 + 1]);
                    MMA_BF16(d, pal, vfh[sub * 2], vfh[sub * 2 + 1]);
                    MMA_BF16(d, pah, vfl[sub * 2], vfl[sub * 2 + 1]);
                }
            }
        }
    }

    // ---- normalize + write ctx [t*8+b][1024] fp32 ----
    const float inv1 = 1.0f / l1, inv2 = 1.0f / l2;
    const int t1 = q0 + wid * 16 + (lane >> 2);
    const int bb = head >> 4, hh = head & 15;
    const int colb = hh * 64 + 2 * (lane & 3);
    #pragma unroll
    for (int nb = 0; nb < 8; nb++) {
        int col = colb + nb * 8;
        size_t o1 = ((size_t)t1 * 8 + bb) * 1024 + col;
        float2 w0 = make_float2(oacc[nb][0] * inv1, oacc[nb][1] * inv1);
        float2 w1 = make_float2(oacc[nb][2] * inv2, oacc[nb][3] * inv2);
        *(float2*)&ctx[o1] = w0;
        *(float2*)&ctx[o1 + 65536] = w1;   // t1+8 -> m+64 rows
    }
}

// ===========================================================================
// Launch
// ===========================================================================
extern "C" void kernel_launch(void* const* d_in, const int* in_sizes, int n_in,
                              void* d_out, int out_size) {
    const float* query = (const float*)d_in[0];
    const float* key   = (const float*)d_in[1];
    const float* value = (const float*)d_in[2];
    const float* Wq = (const float*)d_in[3];
    const float* bq = (const float*)d_in[4];
    const float* Wk = (const float*)d_in[5];
    const float* bk = (const float*)d_in[6];
    const float* Wv = (const float*)d_in[7];
    const float* bv = (const float*)d_in[8];
    const float* Wo = (const float*)d_in[9];
    const float* bo = (const float*)d_in[10];
    float* out = (float*)d_out;

    __nv_bfloat16 *pqh, *pql, *pkh, *pkl, *pvh, *pvl;
    float* cb;
    cudaGetSymbolAddress((void**)&pqh, g_qh);
    cudaGetSymbolAddress((void**)&pql, g_ql);
    cudaGetSymbolAddress((void**)&pkh, g_kh);
    cudaGetSymbolAddress((void**)&pkl, g_kl);
    cudaGetSymbolAddress((void**)&pvh, g_vh);
    cudaGetSymbolAddress((void**)&pvl, g_vl);
    cudaGetSymbolAddress((void**)&cb, g_ctx);

    cudaFuncSetAttribute(gemm_tc_kernel,
                         cudaFuncAttributeMaxDynamicSharedMemorySize, GEMM_SMEM);
    cudaFuncSetAttribute(attn_tc_kernel,
                         cudaFuncAttributeMaxDynamicSharedMemorySize, ATTN_SMEM);

    dim3 gemm_grid(1024 / 128, M_ROWS / 128);   // (8, 64)
    gemm_tc_kernel<<<gemm_grid, 256, GEMM_SMEM>>>(query, Wq, bq, nullptr,
                                                  pqh, pql, 0.125f);
    gemm_tc_kernel<<<gemm_grid, 256, GEMM_SMEM>>>(key, Wk, bk, nullptr,
                                                  pkh, pkl, 1.0f);
    gemm_tc_kernel<<<gemm_grid, 256, GEMM_SMEM>>>(value, Wv, bv, nullptr,
                                                  pvh, pvl, 1.0f);

    dim3 attn_grid(T_DIM / 128, B_DIM * H_DIM);  // (8, 128)
    attn_tc_kernel<<<attn_grid, 256, ATTN_SMEM>>>(pqh, pql, pkh, pkl,
                                                  pvh, pvl, cb);

    gemm_tc_kernel<<<gemm_grid, 256, GEMM_SMEM>>>(cb, Wo, bo, out,
                                                  nullptr, nullptr, 1.0f);
}